// round 11
// baseline (speedup 1.0000x reference)
#include <cuda_runtime.h>
#include <cuda_fp16.h>
#include <cstdint>

#define TOKENS   64
#define NFEAT    8192
#define KFEAT    8192

#define KSPLIT    4
#define K_PER_CTA (KFEAT / KSPLIT)      // 2048 codes
#define CTA_N     128                   // 8 warps x 16 channels
#define ITER_C    64                    // codes per iteration
#define NITER     (K_PER_CTA / ITER_C)  // 32
#define PITCH     72                    // halves per smem A row (144B, conflict-free)
#define ASTAGES   4

// scratch
__device__ __align__(16) __half g_x16[TOKENS * KFEAT];            // 1MB, K-permuted fp16 x
__device__ float g_sumx[TOKENS];
__device__ __align__(16) float g_part[KSPLIT][TOKENS * NFEAT];    // 8MB
__device__ unsigned g_tilecnt[NFEAT / CTA_N];                     // per-tile finalize counters

// ---------------------------------------------------------------------------
// Prep: x16 with per-16-group permutation sigma(j)=((j>>3)&1)*2+(j&1)+((j>>1)&3)*4
// ---------------------------------------------------------------------------
__global__ __launch_bounds__(512) void prep_kernel(const float* __restrict__ x) {
    __shared__ float s_w[16];
    const int t = blockIdx.x, tid = threadIdx.x;
    const int g = tid;                           // 16-code group index (0..511)
    const float* xr = x + (size_t)t * KFEAT;
    float4 f[4];
#pragma unroll
    for (int i = 0; i < 4; i++)
        f[i] = reinterpret_cast<const float4*>(xr + g * 16)[i];
    float v[16];
#pragma unroll
    for (int i = 0; i < 4; i++) {
        v[i * 4 + 0] = f[i].x; v[i * 4 + 1] = f[i].y;
        v[i * 4 + 2] = f[i].z; v[i * 4 + 3] = f[i].w;
    }
    float sm = 0.f;
    unsigned short w[16];
#pragma unroll
    for (int j = 0; j < 16; j++) {
        int s = ((j >> 3) & 1) * 2 + (j & 1) + ((j >> 1) & 3) * 4;
        __half h = __float2half_rn(v[s]);
        sm += __half2float(h);
        w[j] = __half_as_ushort(h);
    }
    uint4* dst = reinterpret_cast<uint4*>(g_x16 + (size_t)t * KFEAT + g * 16);
    dst[0] = make_uint4((uint32_t)w[0] | ((uint32_t)w[1] << 16),
                        (uint32_t)w[2] | ((uint32_t)w[3] << 16),
                        (uint32_t)w[4] | ((uint32_t)w[5] << 16),
                        (uint32_t)w[6] | ((uint32_t)w[7] << 16));
    dst[1] = make_uint4((uint32_t)w[8] | ((uint32_t)w[9] << 16),
                        (uint32_t)w[10] | ((uint32_t)w[11] << 16),
                        (uint32_t)w[12] | ((uint32_t)w[13] << 16),
                        (uint32_t)w[14] | ((uint32_t)w[15] << 16));
#pragma unroll
    for (int o = 16; o > 0; o >>= 1) sm += __shfl_xor_sync(0xFFFFFFFFu, sm, o);
    if ((tid & 31) == 0) s_w[tid >> 5] = sm;
    __syncthreads();
    if (tid < 32) {
        float r = (tid < 16) ? s_w[tid] : 0.f;
#pragma unroll
        for (int o = 8; o > 0; o >>= 1) r += __shfl_xor_sync(0xFFFFFFFFu, r, o);
        if (tid == 0) g_sumx[t] = r;
    }
}

// ---------------------------------------------------------------------------
__device__ __forceinline__ void cpa16(uint32_t dst, const void* src) {
    asm volatile("cp.async.ca.shared.global [%0], [%1], 16;\n" :: "r"(dst), "l"(src));
}
#define CP_COMMIT() asm volatile("cp.async.commit_group;\n" ::: "memory")
#define CP_WAIT2()  asm volatile("cp.async.wait_group 2;\n" ::: "memory")

__device__ __forceinline__ int4 ldg_cs(const int* p) {
    int4 v;
    asm volatile("ld.global.cs.v4.b32 {%0,%1,%2,%3}, [%4];"
        : "=r"(v.x), "=r"(v.y), "=r"(v.z), "=r"(v.w) : "l"(p));
    return v;
}
__device__ __forceinline__ void pf_l2(const void* p) {
    asm volatile("prefetch.global.L2 [%0];" :: "l"(p));
}
// [a.b0, 0, b.b0, 0] -> half2 {ca*2^-24, cb*2^-24} (exact), one PRMT.
__device__ __forceinline__ uint32_t pack2(uint32_t a, uint32_t b) {
    uint32_t r;
    asm("prmt.b32 %0, %1, %2, 0x5410;" : "=r"(r) : "r"(a), "r"(b));
    return r;
}
__device__ __forceinline__ void mma16816(float* d, const uint32_t* a, uint32_t b0, uint32_t b1) {
    asm volatile(
        "mma.sync.aligned.m16n8k16.row.col.f32.f16.f16.f32 "
        "{%0,%1,%2,%3},{%4,%5,%6,%7},{%8,%9},{%0,%1,%2,%3};"
        : "+f"(d[0]), "+f"(d[1]), "+f"(d[2]), "+f"(d[3])
        : "r"(a[0]), "r"(a[1]), "r"(a[2]), "r"(a[3]), "r"(b0), "r"(b1));
}

// ---------------------------------------------------------------------------
// GEMM + fused finalize. 64tok x 128ch x 2048codes per CTA; 256 CTAs, 2/SM.
// ---------------------------------------------------------------------------
__global__ __launch_bounds__(256, 2) void gemm_kernel(
    const int* __restrict__ q, const float* __restrict__ scales,
    const int* __restrict__ zp, const float* __restrict__ bias,
    float* __restrict__ out) {

    __shared__ __align__(16) __half sA[ASTAGES][TOKENS * PITCH];   // 4 x 9216 B
    __shared__ unsigned s_cnt;

    const int tid  = threadIdx.x;
    const int warp = tid >> 5;
    const int lane = tid & 31;
    const int bx = blockIdx.x, by = blockIdx.y;

    const int n0 = bx * CTA_N + warp * 16;
    const int kb = by * K_PER_CTA;

    const int r0 = n0 + (lane >> 2);
    const int r1 = r0 + 8;
    const int qd4 = (lane & 3) * 4;

    const int* pB0 = q + (size_t)r0 * KFEAT + kb + qd4;
    const int* pB1 = q + (size_t)r1 * KFEAT + kb + qd4;
    const int pfo = (lane & 1) * 32 - qd4;     // line-spread prefetch offset

    // A staging: 64 rows x 64 halves (128B) per iter; 256 thr x 32B (2 segs)
    const int arow = tid >> 2;
    const int aseg = tid & 3;
    const __half* asrc = g_x16 + (size_t)arow * KFEAT + kb + aseg * 8;
    const uint32_t sbase = (uint32_t)__cvta_generic_to_shared(&sA[0][0]);
    const uint32_t ABUF  = TOKENS * PITCH * 2;
    const uint32_t adst  = (uint32_t)(arow * PITCH + aseg * 8) * 2;

    // L2 prefetch for iters 1,2
    pf_l2(pB0 + ITER_C + pfo);     pf_l2(pB1 + ITER_C + pfo);
    pf_l2(pB0 + 2 * ITER_C + pfo); pf_l2(pB1 + 2 * ITER_C + pfo);

    // B registers: one iteration (64 codes) = [nf][s], s=0..3
    int4 raw[2][4];
#pragma unroll
    for (int s = 0; s < 4; s++) {
        raw[0][s] = ldg_cs(pB0 + s * 16);
        raw[1][s] = ldg_cs(pB1 + s * 16);
    }
    // A cp.async prologue: iters 0,1,2
#pragma unroll
    for (int i = 0; i < 3; i++) {
        cpa16(sbase + i * ABUF + adst, asrc + (size_t)i * ITER_C);
        cpa16(sbase + i * ABUF + adst + 64, asrc + (size_t)i * ITER_C + 32);
        CP_COMMIT();
    }

    float acc[4][2][4];
#pragma unroll
    for (int mi = 0; mi < 4; mi++)
#pragma unroll
        for (int nf = 0; nf < 2; nf++)
#pragma unroll
            for (int j = 0; j < 4; j++) acc[mi][nf][j] = 0.f;

    const int rl = lane & 15;
    const int kh = (lane >> 4) * 8;

    for (int i = 0; i < NITER; i++) {
        CP_WAIT2();
        __syncthreads();

        // A for iter i+3
        if (i + 3 < NITER) {
            const __half* s3 = asrc + (size_t)(i + 3) * ITER_C;
            cpa16(sbase + ((i + 3) & 3) * ABUF + adst, s3);
            cpa16(sbase + ((i + 3) & 3) * ABUF + adst + 64, s3 + 32);
        }
        CP_COMMIT();

        // L2 prefetch 3 iters ahead (lines land before demand LDGs at i+3... i+1 issue)
        if (i + 3 < NITER) {
            pf_l2(pB0 + (i + 3) * ITER_C + pfo);
            pf_l2(pB1 + (i + 3) * ITER_C + pfo);
        }

        const uint32_t abase = sbase + (uint32_t)(i & 3) * ABUF;
        const int off = (i + 1) * ITER_C;
        const bool more = (i + 1 < NITER);

#pragma unroll
        for (int s = 0; s < 4; s++) {
            uint32_t bf00 = pack2((uint32_t)raw[0][s].x, (uint32_t)raw[0][s].y);
            uint32_t bf01 = pack2((uint32_t)raw[0][s].z, (uint32_t)raw[0][s].w);
            uint32_t bf10 = pack2((uint32_t)raw[1][s].x, (uint32_t)raw[1][s].y);
            uint32_t bf11 = pack2((uint32_t)raw[1][s].z, (uint32_t)raw[1][s].w);

            if (more) {
                raw[0][s] = ldg_cs(pB0 + off + s * 16);
                raw[1][s] = ldg_cs(pB1 + off + s * 16);
            }

            uint32_t a[4][4];
#pragma unroll
            for (int mi = 0; mi < 4; mi++) {
                uint32_t addr = abase + (uint32_t)((mi * 16 + rl) * PITCH + s * 16 + kh) * 2;
                asm volatile(
                    "ldmatrix.sync.aligned.m8n8.x4.shared.b16 {%0,%1,%2,%3}, [%4];"
                    : "=r"(a[mi][0]), "=r"(a[mi][1]), "=r"(a[mi][2]), "=r"(a[mi][3])
                    : "r"(addr));
            }
#pragma unroll
            for (int mi = 0; mi < 4; mi++) {
                mma16816(acc[mi][0], a[mi], bf00, bf01);
                mma16816(acc[mi][1], a[mi], bf10, bf11);
            }
        }
    }

    // epilogue: raw partial dots
    {
        float* pp = &g_part[by][0];
        const int kc2 = (lane & 3) * 2;
#pragma unroll
        for (int mi = 0; mi < 4; mi++)
#pragma unroll
            for (int nf = 0; nf < 2; nf++) {
                int col = n0 + nf * 8 + kc2;
                int t0  = mi * 16 + (lane >> 2);
                *reinterpret_cast<float2*>(&pp[(size_t)t0 * NFEAT + col]) =
                    make_float2(acc[mi][nf][0], acc[mi][nf][1]);
                *reinterpret_cast<float2*>(&pp[(size_t)(t0 + 8) * NFEAT + col]) =
                    make_float2(acc[mi][nf][2], acc[mi][nf][3]);
            }
    }

    // fused finalize: last of the 4 K-split CTAs for tile bx reduces + scales.
    __threadfence();
    __syncthreads();
    if (tid == 0) s_cnt = atomicAdd(&g_tilecnt[bx], 1u);
    __syncthreads();
    if ((s_cnt & 3u) == 3u) {
        __threadfence();
        const float SC = 16777216.0f;  // 2^24
        for (int i = tid; i < TOKENS * (CTA_N / 4); i += 256) {
            int t  = i >> 5;                      // token
            int c4 = i & 31;                      // float4 within tile
            size_t idx = (size_t)t * (NFEAT / 4) + bx * (CTA_N / 4) + c4;
            float4 a = reinterpret_cast<const float4*>(g_part[0])[idx];
            float4 b = reinterpret_cast<const float4*>(g_part[1])[idx];
            float4 c = reinterpret_cast<const float4*>(g_part[2])[idx];
            float4 d = reinterpret_cast<const float4*>(g_part[3])[idx];
            int gcol4 = bx * (CTA_N / 4) + c4;
            float4 sc = reinterpret_cast<const float4*>(scales)[gcol4];
            float4 bi = reinterpret_cast<const float4*>(bias)[gcol4];
            int4   zi = reinterpret_cast<const int4*>(zp)[gcol4];
            float sx = g_sumx[t];
            float4 r;
            r.x = bi.x + sc.x * (SC * ((a.x + b.x) + (c.x + d.x)) - (float)zi.x * sx);
            r.y = bi.y + sc.y * (SC * ((a.y + b.y) + (c.y + d.y)) - (float)zi.y * sx);
            r.z = bi.z + sc.z * (SC * ((a.z + b.z) + (c.z + d.z)) - (float)zi.z * sx);
            r.w = bi.w + sc.w * (SC * ((a.w + b.w) + (c.w + d.w)) - (float)zi.w * sx);
            reinterpret_cast<float4*>(out)[idx] = r;
        }
    }
}

// ---------------------------------------------------------------------------
extern "C" void kernel_launch(void* const* d_in, const int* in_sizes, int n_in,
                              void* d_out, int out_size) {
    const float* x    = (const float*)d_in[0];
    const int*   qw   = (const int*)d_in[1];
    const float* sc   = (const float*)d_in[2];
    const int*   zp   = (const int*)d_in[3];
    const float* bias = (const float*)d_in[4];
    float*       out  = (float*)d_out;
    (void)in_sizes; (void)n_in; (void)out_size;

    prep_kernel<<<TOKENS, 512>>>(x);
    gemm_kernel<<<dim3(NFEAT / CTA_N, KSPLIT), 256>>>(qw, sc, zp, bias, out);
}

// round 12
// speedup vs baseline: 1.0705x; 1.0705x over previous
#include <cuda_runtime.h>
#include <cuda_fp16.h>
#include <cstdint>

#define TOKENS   64
#define NFEAT    8192
#define KFEAT    8192

#define KSPLIT    4
#define K_PER_CTA (KFEAT / KSPLIT)      // 2048 codes
#define CTA_N     128                   // 8 warps x 16 channels
#define ITER_C    64                    // codes per iteration
#define NITER     (K_PER_CTA / ITER_C)  // 32
#define PITCH     72                    // halves per smem row (144B, conflict-free)
#define NSTAGE    3

#define B_STAGE   (CTA_N * PITCH * 2)   // 18432 B (128 rows x 144B)
#define A_STAGE   (TOKENS * PITCH * 2)  // 9216 B
#define A_BASE    (NSTAGE * B_STAGE)    // 55296
#define SMEM_TOTAL (A_BASE + NSTAGE * A_STAGE)  // 82944

// scratch
__device__ __align__(16) __half g_x16[TOKENS * KFEAT];            // 1MB fp16 x (natural order)
__device__ float g_sumx[TOKENS];
__device__ __align__(16) float g_part[KSPLIT][TOKENS * NFEAT];    // 8MB

// ---------------------------------------------------------------------------
// Prep: plain fp16 convert (natural order) + token sums.
// ---------------------------------------------------------------------------
__global__ __launch_bounds__(512) void prep_kernel(const float* __restrict__ x) {
    __shared__ float s_w[16];
    const int t = blockIdx.x, tid = threadIdx.x;
    const float4* xr = reinterpret_cast<const float4*>(x + (size_t)t * KFEAT);
    uint4* dst = reinterpret_cast<uint4*>(g_x16 + (size_t)t * KFEAT);
    float sm = 0.f;
#pragma unroll
    for (int i = 0; i < 4; i++) {
        float4 f = xr[tid * 4 + i];
        __half2 h0 = __floats2half2_rn(f.x, f.y);
        __half2 h1 = __floats2half2_rn(f.z, f.w);
        sm += (__low2float(h0) + __high2float(h0)) + (__low2float(h1) + __high2float(h1));
        if (i == 0) dst[tid * 2].x = *(uint32_t*)&h0, dst[tid * 2].y = *(uint32_t*)&h1;
        else if (i == 1) dst[tid * 2].z = *(uint32_t*)&h0, dst[tid * 2].w = *(uint32_t*)&h1;
        else if (i == 2) dst[tid * 2 + 1].x = *(uint32_t*)&h0, dst[tid * 2 + 1].y = *(uint32_t*)&h1;
        else dst[tid * 2 + 1].z = *(uint32_t*)&h0, dst[tid * 2 + 1].w = *(uint32_t*)&h1;
    }
#pragma unroll
    for (int o = 16; o > 0; o >>= 1) sm += __shfl_xor_sync(0xFFFFFFFFu, sm, o);
    if ((tid & 31) == 0) s_w[tid >> 5] = sm;
    __syncthreads();
    if (tid < 32) {
        float r = (tid < 16) ? s_w[tid] : 0.f;
#pragma unroll
        for (int o = 8; o > 0; o >>= 1) r += __shfl_xor_sync(0xFFFFFFFFu, r, o);
        if (tid == 0) g_sumx[t] = r;
    }
}

// ---------------------------------------------------------------------------
__device__ __forceinline__ void cpa16(uint32_t dst, const void* src) {
    asm volatile("cp.async.ca.shared.global [%0], [%1], 16;\n" :: "r"(dst), "l"(src));
}
#define CP_COMMIT() asm volatile("cp.async.commit_group;\n" ::: "memory")
#define CP_WAIT1()  asm volatile("cp.async.wait_group 1;\n" ::: "memory")

__device__ __forceinline__ int4 ldg_cs(const int* p) {
    int4 v;
    asm volatile("ld.global.cs.v4.b32 {%0,%1,%2,%3}, [%4];"
        : "=r"(v.x), "=r"(v.y), "=r"(v.z), "=r"(v.w) : "l"(p));
    return v;
}
// [a.b0, 0, b.b0, 0] -> half2 {ca*2^-24, cb*2^-24} (exact), one PRMT.
__device__ __forceinline__ uint32_t pack2(uint32_t a, uint32_t b) {
    uint32_t r;
    asm("prmt.b32 %0, %1, %2, 0x5410;" : "=r"(r) : "r"(a), "r"(b));
    return r;
}
__device__ __forceinline__ void mma16816(float* d, const uint32_t* a, uint32_t b0, uint32_t b1) {
    asm volatile(
        "mma.sync.aligned.m16n8k16.row.col.f32.f16.f16.f32 "
        "{%0,%1,%2,%3},{%4,%5,%6,%7},{%8,%9},{%0,%1,%2,%3};"
        : "+f"(d[0]), "+f"(d[1]), "+f"(d[2]), "+f"(d[3])
        : "r"(a[0]), "r"(a[1]), "r"(a[2]), "r"(a[3]), "r"(b0), "r"(b1));
}
#define LDSM4(R0, R1, R2, R3, addr)                                            \
    asm volatile("ldmatrix.sync.aligned.m8n8.x4.shared.b16 {%0,%1,%2,%3}, [%4];" \
        : "=r"(R0), "=r"(R1), "=r"(R2), "=r"(R3) : "r"(addr))

// ---------------------------------------------------------------------------
// GEMM: coalesced B (nL=4) -> PRMT pack -> smem -> ldmatrix fragments.
// ---------------------------------------------------------------------------
__global__ __launch_bounds__(256, 2) void gemm_kernel(const int* __restrict__ q) {
    extern __shared__ __align__(16) uint8_t smem[];
    const int tid  = threadIdx.x;
    const int warp = tid >> 5;
    const int lane = tid & 31;
    const uint32_t sbase = (uint32_t)__cvta_generic_to_shared(smem);

    const int blockN = blockIdx.x * CTA_N;
    const int kb = blockIdx.y * K_PER_CTA;

    // ---- B producer mapping: thread covers 8 chunks (row = crow+16j, 16B c)
    const int crow = tid >> 4;          // base row 0..15
    const int cc   = tid & 15;          // 16B chunk within row's 256B
    const int* pB = q + (size_t)(blockN + crow) * KFEAT + kb + cc * 4;
    const uint32_t sts_off = (uint32_t)(crow * (PITCH * 2) + cc * 8);

    // ---- A producer mapping
    const int arow = tid >> 2;
    const int aseg = tid & 3;
    const __half* asrc = g_x16 + (size_t)arow * KFEAT + kb + aseg * 8;
    const uint32_t adst = (uint32_t)(arow * PITCH + aseg * 8) * 2;

#define LDG_RAW(it) do {                                                        \
    _Pragma("unroll")                                                           \
    for (int j = 0; j < 8; j++)                                                 \
        raw[j] = ldg_cs(pB + (size_t)j * 16 * KFEAT + (it) * ITER_C);           \
} while (0)

#define STS_RAW(st_) do {                                                       \
    _Pragma("unroll")                                                           \
    for (int j = 0; j < 8; j++) {                                               \
        uint32_t p0 = pack2((uint32_t)raw[j].x, (uint32_t)raw[j].y);            \
        uint32_t p1 = pack2((uint32_t)raw[j].z, (uint32_t)raw[j].w);            \
        asm volatile("st.shared.v2.b32 [%0], {%1,%2};"                          \
            :: "r"((st_) + sts_off + (uint32_t)(j * 16 * PITCH * 2)),           \
               "r"(p0), "r"(p1) : "memory");                                    \
    }                                                                           \
} while (0)

    int4 raw[8];
    // prologue: B stage 0 packed, raw for iter 1, A stages 0,1
    LDG_RAW(0);
    STS_RAW(sbase);
    LDG_RAW(1);
#pragma unroll
    for (int i = 0; i < 2; i++) {
        cpa16(sbase + A_BASE + i * A_STAGE + adst, asrc + (size_t)i * ITER_C);
        cpa16(sbase + A_BASE + i * A_STAGE + adst + 64, asrc + (size_t)i * ITER_C + 32);
        CP_COMMIT();
    }

    float acc[4][2][4];
#pragma unroll
    for (int mi = 0; mi < 4; mi++)
#pragma unroll
        for (int nf = 0; nf < 2; nf++)
#pragma unroll
            for (int j = 0; j < 4; j++) acc[mi][nf][j] = 0.f;

    const int rl = lane & 15;
    const int kh = (lane >> 4) * 8;
    // B ldmatrix address pieces: quad = lane>>3
    const int bq = lane >> 3;
    const uint32_t brow_off =
        (uint32_t)((warp * 16 + (bq >> 1) * 8 + (lane & 7)) * (PITCH * 2) + (bq & 1) * 16);

    int sb = 0, sn = 1;  // stage indices: current, next (mod 3)
    for (int i = 0; i < NITER; i++) {
        CP_WAIT1();
        __syncthreads();

        int s2 = sn + 1; if (s2 == NSTAGE) s2 = 0;       // stage for iter i+2
        if (i + 2 < NITER) {
            const __half* sA2 = asrc + (size_t)(i + 2) * ITER_C;
            cpa16(sbase + A_BASE + s2 * A_STAGE + adst, sA2);
            cpa16(sbase + A_BASE + s2 * A_STAGE + adst + 64, sA2 + 32);
        }
        CP_COMMIT();

        if (i + 1 < NITER) STS_RAW(sbase + (uint32_t)sn * B_STAGE);
        if (i + 2 < NITER) LDG_RAW(i + 2);

        const uint32_t bstg = sbase + (uint32_t)sb * B_STAGE;
        const uint32_t astg = sbase + A_BASE + (uint32_t)sb * A_STAGE;

#pragma unroll
        for (int s = 0; s < 4; s++) {
            uint32_t b0, b1, b2, b3;
            LDSM4(b0, b1, b2, b3, bstg + brow_off + (uint32_t)(s * 32));
            uint32_t a[4][4];
#pragma unroll
            for (int mi = 0; mi < 4; mi++) {
                uint32_t addr = astg + (uint32_t)((mi * 16 + rl) * PITCH + s * 16 + kh) * 2;
                LDSM4(a[mi][0], a[mi][1], a[mi][2], a[mi][3], addr);
            }
#pragma unroll
            for (int mi = 0; mi < 4; mi++) {
                mma16816(acc[mi][0], a[mi], b0, b1);
                mma16816(acc[mi][1], a[mi], b2, b3);
            }
        }
        sb = sn; sn = s2;
    }

    // epilogue: raw partial dots
    float* pp = &g_part[blockIdx.y][0];
    const int kc2 = (lane & 3) * 2;
#pragma unroll
    for (int mi = 0; mi < 4; mi++)
#pragma unroll
        for (int nf = 0; nf < 2; nf++) {
            int col = blockN + warp * 16 + nf * 8 + kc2;
            int t0  = mi * 16 + (lane >> 2);
            *reinterpret_cast<float2*>(&pp[(size_t)t0 * NFEAT + col]) =
                make_float2(acc[mi][nf][0], acc[mi][nf][1]);
            *reinterpret_cast<float2*>(&pp[(size_t)(t0 + 8) * NFEAT + col]) =
                make_float2(acc[mi][nf][2], acc[mi][nf][3]);
        }
#undef LDG_RAW
#undef STS_RAW
}

// ---------------------------------------------------------------------------
// Reduce: y = s * (2^24 * sum_splits - zp * sumx_t) + bias
// ---------------------------------------------------------------------------
__global__ void reduce_kernel(const float* __restrict__ scales,
                              const int* __restrict__ zp,
                              const float* __restrict__ bias,
                              float* __restrict__ out) {
    int i = blockIdx.x * blockDim.x + threadIdx.x;     // float4 units
    int col4 = i & (NFEAT / 4 - 1);
    int t    = i >> 11;
    float4 a = reinterpret_cast<const float4*>(g_part[0])[i];
    float4 b = reinterpret_cast<const float4*>(g_part[1])[i];
    float4 c = reinterpret_cast<const float4*>(g_part[2])[i];
    float4 d = reinterpret_cast<const float4*>(g_part[3])[i];
    float4 sc = reinterpret_cast<const float4*>(scales)[col4];
    float4 bi = reinterpret_cast<const float4*>(bias)[col4];
    int4   zi = reinterpret_cast<const int4*>(zp)[col4];
    float sx = g_sumx[t];
    const float SC = 16777216.0f;  // 2^24
    float4 r;
    r.x = bi.x + sc.x * (SC * ((a.x + b.x) + (c.x + d.x)) - (float)zi.x * sx);
    r.y = bi.y + sc.y * (SC * ((a.y + b.y) + (c.y + d.y)) - (float)zi.y * sx);
    r.z = bi.z + sc.z * (SC * ((a.z + b.z) + (c.z + d.z)) - (float)zi.z * sx);
    r.w = bi.w + sc.w * (SC * ((a.w + b.w) + (c.w + d.w)) - (float)zi.w * sx);
    reinterpret_cast<float4*>(out)[i] = r;
}

// ---------------------------------------------------------------------------
extern "C" void kernel_launch(void* const* d_in, const int* in_sizes, int n_in,
                              void* d_out, int out_size) {
    const float* x    = (const float*)d_in[0];
    const int*   qw   = (const int*)d_in[1];
    const float* sc   = (const float*)d_in[2];
    const int*   zp   = (const int*)d_in[3];
    const float* bias = (const float*)d_in[4];
    float*       out  = (float*)d_out;
    (void)in_sizes; (void)n_in; (void)out_size;

    cudaFuncSetAttribute(gemm_kernel, cudaFuncAttributeMaxDynamicSharedMemorySize, SMEM_TOTAL);

    prep_kernel<<<TOKENS, 512>>>(x);
    gemm_kernel<<<dim3(NFEAT / CTA_N, KSPLIT), 256, SMEM_TOTAL>>>(qw);
    reduce_kernel<<<(TOKENS * NFEAT / 4) / 256, 256>>>(sc, zp, bias, out);
}

// round 14
// speedup vs baseline: 1.1141x; 1.0407x over previous
#include <cuda_runtime.h>
#include <cuda_fp16.h>
#include <cstdint>

#define TOKENS   64
#define NFEAT    8192
#define KFEAT    8192

#define CTA_N     128                   // 8 warps x 16 channels
#define ITER_C    64                    // codes per iteration
#define PITCH     72                    // halves per smem row (144B, conflict-free)
#define NSTAGE    3
#define NSLICE    5

#define B_STAGE   (CTA_N * PITCH * 2)   // 18432 B
#define A_STAGE   (TOKENS * PITCH * 2)  // 9216 B
#define A_BASE    (NSTAGE * B_STAGE)    // 55296
#define SMEM_TOTAL (A_BASE + NSTAGE * A_STAGE)  // 82944

// scratch
__device__ __align__(16) __half g_x16[TOKENS * KFEAT];              // 1MB fp16 x
__device__ float g_sumx[TOKENS];
__device__ __align__(16) float g_part[NSLICE][TOKENS * NFEAT];      // 10MB

// ---------------------------------------------------------------------------
// Prep: plain fp16 convert + token sums.
// ---------------------------------------------------------------------------
__global__ __launch_bounds__(512) void prep_kernel(const float* __restrict__ x) {
    __shared__ float s_w[16];
    const int t = blockIdx.x, tid = threadIdx.x;
    const float4* xr = reinterpret_cast<const float4*>(x + (size_t)t * KFEAT);
    uint4* dst = reinterpret_cast<uint4*>(g_x16 + (size_t)t * KFEAT);
    float sm = 0.f;
    uint4 o0, o1;
    {
        float4 f = xr[tid * 4 + 0];
        __half2 h0 = __floats2half2_rn(f.x, f.y), h1 = __floats2half2_rn(f.z, f.w);
        sm += (__low2float(h0) + __high2float(h0)) + (__low2float(h1) + __high2float(h1));
        o0.x = *(uint32_t*)&h0; o0.y = *(uint32_t*)&h1;
        f = xr[tid * 4 + 1];
        h0 = __floats2half2_rn(f.x, f.y); h1 = __floats2half2_rn(f.z, f.w);
        sm += (__low2float(h0) + __high2float(h0)) + (__low2float(h1) + __high2float(h1));
        o0.z = *(uint32_t*)&h0; o0.w = *(uint32_t*)&h1;
        f = xr[tid * 4 + 2];
        h0 = __floats2half2_rn(f.x, f.y); h1 = __floats2half2_rn(f.z, f.w);
        sm += (__low2float(h0) + __high2float(h0)) + (__low2float(h1) + __high2float(h1));
        o1.x = *(uint32_t*)&h0; o1.y = *(uint32_t*)&h1;
        f = xr[tid * 4 + 3];
        h0 = __floats2half2_rn(f.x, f.y); h1 = __floats2half2_rn(f.z, f.w);
        sm += (__low2float(h0) + __high2float(h0)) + (__low2float(h1) + __high2float(h1));
        o1.z = *(uint32_t*)&h0; o1.w = *(uint32_t*)&h1;
    }
    dst[tid * 2] = o0; dst[tid * 2 + 1] = o1;
#pragma unroll
    for (int o = 16; o > 0; o >>= 1) sm += __shfl_xor_sync(0xFFFFFFFFu, sm, o);
    if ((tid & 31) == 0) s_w[tid >> 5] = sm;
    __syncthreads();
    if (tid < 32) {
        float r = (tid < 16) ? s_w[tid] : 0.f;
#pragma unroll
        for (int o = 8; o > 0; o >>= 1) r += __shfl_xor_sync(0xFFFFFFFFu, r, o);
        if (tid == 0) g_sumx[t] = r;
    }
}

// ---------------------------------------------------------------------------
__device__ __forceinline__ void cpa16(uint32_t dst, const void* src) {
    asm volatile("cp.async.ca.shared.global [%0], [%1], 16;\n" :: "r"(dst), "l"(src));
}
#define CP_COMMIT() asm volatile("cp.async.commit_group;\n" ::: "memory")
#define CP_WAIT1()  asm volatile("cp.async.wait_group 1;\n" ::: "memory")

__device__ __forceinline__ int4 ldg_cs(const int* p) {
    int4 v;
    asm volatile("ld.global.cs.v4.b32 {%0,%1,%2,%3}, [%4];"
        : "=r"(v.x), "=r"(v.y), "=r"(v.z), "=r"(v.w) : "l"(p));
    return v;
}
// [a.b0, 0, b.b0, 0] -> half2 {ca*2^-24, cb*2^-24} (exact), one PRMT.
__device__ __forceinline__ uint32_t pack2(uint32_t a, uint32_t b) {
    uint32_t r;
    asm("prmt.b32 %0, %1, %2, 0x5410;" : "=r"(r) : "r"(a), "r"(b));
    return r;
}
__device__ __forceinline__ void mma16816(float* d, const uint32_t* a, uint32_t b0, uint32_t b1) {
    asm volatile(
        "mma.sync.aligned.m16n8k16.row.col.f32.f16.f16.f32 "
        "{%0,%1,%2,%3},{%4,%5,%6,%7},{%8,%9},{%0,%1,%2,%3};"
        : "+f"(d[0]), "+f"(d[1]), "+f"(d[2]), "+f"(d[3])
        : "r"(a[0]), "r"(a[1]), "r"(a[2]), "r"(a[3]), "r"(b0), "r"(b1));
}
#define LDSM4(R0, R1, R2, R3, addr)                                            \
    asm volatile("ldmatrix.sync.aligned.m8n8.x4.shared.b16 {%0,%1,%2,%3}, [%4];" \
        : "=r"(R0), "=r"(R1), "=r"(R2), "=r"(R3) : "r"(addr))

// ---------------------------------------------------------------------------
// GEMM: 296 balanced segments; coalesced B -> PRMT pack -> smem -> ldmatrix.
// ---------------------------------------------------------------------------
__global__ __launch_bounds__(256, 2) void gemm_kernel(const int* __restrict__ q) {
    extern __shared__ __align__(16) uint8_t smem[];
    const int tid  = threadIdx.x;
    const int warp = tid >> 5;
    const int lane = tid & 31;
    const uint32_t sbase = (uint32_t)__cvta_generic_to_shared(smem);

    // ---- balanced segment schedule (bid & bid+148 co-reside per LUT) ----
    const int bid = blockIdx.x;          // 0..295
    const int s = bid % 148, w = bid / 148;
    int tile, start, len, ord;
    if (s < 96 && w == 0) {              // 32-iter segments, tiles 0..23
        tile = s >> 2; ord = s & 3; start = ord * 32; len = 32;
    } else if (s < 80) {                 // w==1: 25-iter segments, tiles 24..63
        tile = 24 + (s >> 1); ord = 3 + (s & 1); start = (s & 1) ? 103 : 78; len = 25;
    } else {                             // 26-iter segments, tiles 24..63
        int k = (s < 96) ? (s - 80) : (16 + 2 * (s - 96) + w);
        tile = 24 + k / 3; ord = k % 3; start = ord * 26; len = 26;
    }

    const int blockN = tile * CTA_N;
    const int kb = start * ITER_C;       // K offset in codes

    // ---- B producer mapping: thread covers 8 chunks (row = crow+16j, 16B c)
    const int crow = tid >> 4;
    const int cc   = tid & 15;
    const int* pB = q + (size_t)(blockN + crow) * KFEAT + kb + cc * 4;
    const uint32_t sts_off = (uint32_t)(crow * (PITCH * 2) + cc * 8);

    // ---- A producer mapping
    const int arow = tid >> 2;
    const int aseg = tid & 3;
    const __half* asrc = g_x16 + (size_t)arow * KFEAT + kb + aseg * 8;
    const uint32_t adst = (uint32_t)(arow * PITCH + aseg * 8) * 2;

#define LDG_RAW(it) do {                                                        \
    _Pragma("unroll")                                                           \
    for (int j = 0; j < 8; j++)                                                 \
        raw[j] = ldg_cs(pB + (size_t)j * 16 * KFEAT + (it) * ITER_C);           \
} while (0)

#define STS_RAW(st_) do {                                                       \
    _Pragma("unroll")                                                           \
    for (int j = 0; j < 8; j++) {                                               \
        uint32_t p0 = pack2((uint32_t)raw[j].x, (uint32_t)raw[j].y);            \
        uint32_t p1 = pack2((uint32_t)raw[j].z, (uint32_t)raw[j].w);            \
        asm volatile("st.shared.v2.b32 [%0], {%1,%2};"                          \
            :: "r"((st_) + sts_off + (uint32_t)(j * 16 * PITCH * 2)),           \
               "r"(p0), "r"(p1) : "memory");                                    \
    }                                                                           \
} while (0)

    int4 raw[8];
    LDG_RAW(0);
    STS_RAW(sbase);
    LDG_RAW(1);
#pragma unroll
    for (int i = 0; i < 2; i++) {
        cpa16(sbase + A_BASE + i * A_STAGE + adst, asrc + (size_t)i * ITER_C);
        cpa16(sbase + A_BASE + i * A_STAGE + adst + 64, asrc + (size_t)i * ITER_C + 32);
        CP_COMMIT();
    }

    float acc[4][2][4];
#pragma unroll
    for (int mi = 0; mi < 4; mi++)
#pragma unroll
        for (int nf = 0; nf < 2; nf++)
#pragma unroll
            for (int j = 0; j < 4; j++) acc[mi][nf][j] = 0.f;

    const int rl = lane & 15;
    const int kh = (lane >> 4) * 8;
    const int bq = lane >> 3;
    const uint32_t brow_off =
        (uint32_t)((warp * 16 + (bq >> 1) * 8 + (lane & 7)) * (PITCH * 2) + (bq & 1) * 16);

    int sb = 0, sn = 1;
    for (int i = 0; i < len; i++) {
        CP_WAIT1();
        __syncthreads();

        int s2 = sn + 1; if (s2 == NSTAGE) s2 = 0;
        if (i + 2 < len) {
            const __half* sA2 = asrc + (size_t)(i + 2) * ITER_C;
            cpa16(sbase + A_BASE + s2 * A_STAGE + adst, sA2);
            cpa16(sbase + A_BASE + s2 * A_STAGE + adst + 64, sA2 + 32);
        }
        CP_COMMIT();

        if (i + 1 < len) STS_RAW(sbase + (uint32_t)sn * B_STAGE);
        if (i + 2 < len) LDG_RAW(i + 2);

        const uint32_t bstg = sbase + (uint32_t)sb * B_STAGE;
        const uint32_t astg = sbase + A_BASE + (uint32_t)sb * A_STAGE;

#pragma unroll
        for (int ss = 0; ss < 4; ss++) {
            uint32_t b0, b1, b2, b3;
            LDSM4(b0, b1, b2, b3, bstg + brow_off + (uint32_t)(ss * 32));
            uint32_t a[4][4];
#pragma unroll
            for (int mi = 0; mi < 4; mi++) {
                uint32_t addr = astg + (uint32_t)((mi * 16 + rl) * PITCH + ss * 16 + kh) * 2;
                LDSM4(a[mi][0], a[mi][1], a[mi][2], a[mi][3], addr);
            }
#pragma unroll
            for (int mi = 0; mi < 4; mi++) {
                mma16816(acc[mi][0], a[mi], b0, b1);
                mma16816(acc[mi][1], a[mi], b2, b3);
            }
        }
        sb = sn; sn = s2;
    }

    // epilogue: raw partial dots into slice `ord`
    float* pp = &g_part[ord][0];
    const int kc2 = (lane & 3) * 2;
#pragma unroll
    for (int mi = 0; mi < 4; mi++)
#pragma unroll
        for (int nf = 0; nf < 2; nf++) {
            int col = blockN + warp * 16 + nf * 8 + kc2;
            int t0  = mi * 16 + (lane >> 2);
            *reinterpret_cast<float2*>(&pp[(size_t)t0 * NFEAT + col]) =
                make_float2(acc[mi][nf][0], acc[mi][nf][1]);
            *reinterpret_cast<float2*>(&pp[(size_t)(t0 + 8) * NFEAT + col]) =
                make_float2(acc[mi][nf][2], acc[mi][nf][3]);
        }
#undef LDG_RAW
#undef STS_RAW
}

// ---------------------------------------------------------------------------
// Reduce: y = s * (2^24 * sum_slices - zp * sumx_t) + bias
// Tiles 0..23 have 4 slices; tiles 24..63 have 5.
// ---------------------------------------------------------------------------
__global__ void reduce_kernel(const float* __restrict__ scales,
                              const int* __restrict__ zp,
                              const float* __restrict__ bias,
                              float* __restrict__ out) {
    int i = blockIdx.x * blockDim.x + threadIdx.x;     // float4 units
    int col4 = i & (NFEAT / 4 - 1);
    int t    = i >> 11;
    float4 a = reinterpret_cast<const float4*>(g_part[0])[i];
    float4 b = reinterpret_cast<const float4*>(g_part[1])[i];
    float4 c = reinterpret_cast<const float4*>(g_part[2])[i];
    float4 d = reinterpret_cast<const float4*>(g_part[3])[i];
    float4 e = make_float4(0.f, 0.f, 0.f, 0.f);
    if (col4 >= 24 * 32) e = reinterpret_cast<const float4*>(g_part[4])[i];
    float4 sc = reinterpret_cast<const float4*>(scales)[col4];
    float4 bi = reinterpret_cast<const float4*>(bias)[col4];
    int4   zi = reinterpret_cast<const int4*>(zp)[col4];
    float sx = g_sumx[t];
    const float SC = 16777216.0f;  // 2^24
    float4 r;
    r.x = bi.x + sc.x * (SC * (((a.x + b.x) + (c.x + d.x)) + e.x) - (float)zi.x * sx);
    r.y = bi.y + sc.y * (SC * (((a.y + b.y) + (c.y + d.y)) + e.y) - (float)zi.y * sx);
    r.z = bi.z + sc.z * (SC * (((a.z + b.z) + (c.z + d.z)) + e.z) - (float)zi.z * sx);
    r.w = bi.w + sc.w * (SC * (((a.w + b.w) + (c.w + d.w)) + e.w) - (float)zi.w * sx);
    reinterpret_cast<float4*>(out)[i] = r;
}

// ---------------------------------------------------------------------------
extern "C" void kernel_launch(void* const* d_in, const int* in_sizes, int n_in,
                              void* d_out, int out_size) {
    const float* x    = (const float*)d_in[0];
    const int*   qw   = (const int*)d_in[1];
    const float* sc   = (const float*)d_in[2];
    const int*   zp   = (const int*)d_in[3];
    const float* bias = (const float*)d_in[4];
    float*       out  = (float*)d_out;
    (void)in_sizes; (void)n_in; (void)out_size;

    cudaFuncSetAttribute(gemm_kernel, cudaFuncAttributeMaxDynamicSharedMemorySize, SMEM_TOTAL);

    prep_kernel<<<TOKENS, 512>>>(x);
    gemm_kernel<<<296, 256, SMEM_TOTAL>>>(qw);
    reduce_kernel<<<(TOKENS * NFEAT / 4) / 256, 256>>>(sc, zp, bias, out);
}